// round 14
// baseline (speedup 1.0000x reference)
#include <cuda_runtime.h>

#define DEVINLINE __device__ __forceinline__

constexpr int BATCH = 100;
constexpr int BPAD  = 128;   // padded batch stride; lanes cover batches

// --- fc coefficient offsets (gates, float4 units) ---
constexpr int OFF_FC1 = 0;        // 20480
constexpr int OFF_FC2 = 20480;    // 10240
constexpr int OFF_FC3 = 30720;    // 5120
constexpr int N_FCC   = 35840;

// conv descriptor slots (float4 units): 9 slots per filter (rewired tree, no picks)
// [0]=offA0..3  [1]=offB0..3  [2..5]=leaf coefs  [6]=midA  [7]=midB  [8]=top
constexpr int DESC_C1 = 0;            // 16 filters
constexpr int DESC_C2 = 16 * 9;       // 48 filters
constexpr int DESC_C3 = 64 * 9;       // 144 filters

// --- scratch (device globals; zero-initialized; halo positions never written) ---
__device__ float4 g_coef[N_FCC];
__device__ float4 g_desc[208 * 9];
__device__ float  g_xT [784 * BPAD];            // binarized input, [pos][BPAD]
__device__ float  g_p1T[16 * 196 * BPAD];       // conv1 pooled, halo=1
__device__ float  g_p2T[48 * 64 * BPAD];        // conv2 pooled, halo=1
__device__ float  g_p3T[1296 * BPAD];           // conv3 pooled (ref flatten order)
__device__ float  g_f1T[20480 * BPAD];
__device__ float  g_f2T[10240 * BPAD];

// softmax(w[16]) -> fused gate coefficients (C, A, B, D):  op = C + A*a + B*b + D*ab
DEVINLINE float4 softcoef(const float* __restrict__ w) {
    const float4* w4 = (const float4*)w;
    float4 q0 = __ldg(w4 + 0), q1 = __ldg(w4 + 1), q2 = __ldg(w4 + 2), q3 = __ldg(w4 + 3);
    float v[16] = {q0.x, q0.y, q0.z, q0.w, q1.x, q1.y, q1.z, q1.w,
                   q2.x, q2.y, q2.z, q2.w, q3.x, q3.y, q3.z, q3.w};
    float mx = -1e30f;
    #pragma unroll
    for (int i = 0; i < 16; i++) mx = fmaxf(mx, v[i]);
    float sum = 0.f;
    #pragma unroll
    for (int i = 0; i < 16; i++) { v[i] = __expf(v[i] - mx); sum += v[i]; }
    float inv = 1.0f / sum;
    #pragma unroll
    for (int i = 0; i < 16; i++) v[i] *= inv;
    float C = v[8] + v[9] + v[10] + v[11] + v[12] + v[13] + v[14] + v[15];
    float A = v[2] + v[3] + v[6] + v[7] - v[8] - v[9] - v[12] - v[13];
    float B = v[4] + v[5] + v[6] + v[7] - v[8] - v[9] - v[10] - v[11];
    float D = v[1] - v[2] - v[4] - 2.f * v[6] - v[7]
            + v[8] + 2.f * v[9] + v[11] + v[13] - v[14];
    return make_float4(C, A, B, D);
}

DEVINLINE float2 gate2(float2 a, float2 b, float4 k) {
    float2 r;
    r.x = fmaf(a.x, fmaf(k.w, b.x, k.y), fmaf(k.z, b.x, k.x));
    r.y = fmaf(a.y, fmaf(k.w, b.y, k.y), fmaf(k.z, b.y, k.x));
    return r;
}
DEVINLINE float4 gate4(float4 a, float4 b, float4 k) {
    float4 r;
    r.x = fmaf(a.x, fmaf(k.w, b.x, k.y), fmaf(k.z, b.x, k.x));
    r.y = fmaf(a.y, fmaf(k.w, b.y, k.y), fmaf(k.z, b.y, k.x));
    r.z = fmaf(a.z, fmaf(k.w, b.z, k.y), fmaf(k.z, b.z, k.x));
    r.w = fmaf(a.w, fmaf(k.w, b.w, k.y), fmaf(k.z, b.w, k.x));
    return r;
}

// ============================================================================
// Prep kernel: fc coefficients + transpose/binarize + rewired conv descriptors.
// ============================================================================
struct PrepArgs {
    const float* x;
    const float* fc1w; const float* fc2w; const float* fc3w;
    const int*   ci0[3]; const int* ci1[3]; const int* ci2[3];
    const float* cw0[3]; const float* cw1[3]; const float* cw2[3];
};

__constant__ int c_F[3]    = {16, 48, 144};
__constant__ int c_KS[3]   = {5, 3, 3};
__constant__ int c_CSTR[3] = {784, 196, 64};
__constant__ int c_WPAD[3] = {28, 14, 8};
__constant__ int c_DOFF[3] = {DESC_C1, DESC_C2, DESC_C3};

__global__ void prep_kernel(PrepArgs args) {
    int tid = blockIdx.x * blockDim.x + threadIdx.x;
    if (tid < N_FCC) {
        const float* w;
        int g;
        if (tid < OFF_FC2)      { w = args.fc1w; g = tid; }
        else if (tid < OFF_FC3) { w = args.fc2w; g = tid - OFF_FC2; }
        else                    { w = args.fc3w; g = tid - OFF_FC3; }
        g_coef[tid] = softcoef(w + (size_t)g * 16);
    } else if (tid < N_FCC + 208) {
        int j = tid - N_FCC;
        int layer, f;
        if (j < 16)      { layer = 0; f = j; }
        else if (j < 64) { layer = 1; f = j - 16; }
        else             { layer = 2; f = j - 64; }

        int F = c_F[layer], KS = c_KS[layer], CSTR = c_CSTR[layer], WP = c_WPAD[layer];
        const int* i0 = args.ci0[layer];
        const int* i1 = args.ci1[layer];
        const int* i2 = args.ci2[layer];
        float4* dst = g_desc + c_DOFF[layer] + f * 9;

        int a2 = i2[f] & 1;                     // top-a mid index
        int b2 = i2[F + f] & 1;                 // top-b mid index

        // consumed mid-trees in order (duplicate if a2 == b2)
        int mids[2] = {a2, b2};
        int slots[4];   // leaf-gate index (0..3) per slot
        #pragma unroll
        for (int m = 0; m < 2; m++) {
            int mg = mids[m];
            slots[2 * m]     = i1[f * 2 + mg] & 3;          // mid's a-leaf
            slots[2 * m + 1] = i1[F * 2 + f * 2 + mg] & 3;  // mid's b-leaf
        }

        int offA[4], offB[4];
        #pragma unroll
        for (int s = 0; s < 4; s++) {
            int lg = slots[s];
            int ta = i0[f * 4 + lg], tb = i0[F * 4 + f * 4 + lg];
            int ca = ta / (KS * KS), ra = ta - ca * KS * KS;
            int cb = tb / (KS * KS), rb = tb - cb * KS * KS;
            offA[s] = (ca * CSTR + (ra / KS) * WP + (ra % KS)) * BPAD;
            offB[s] = (cb * CSTR + (rb / KS) * WP + (rb % KS)) * BPAD;
            dst[2 + s] = softcoef(args.cw0[layer] + (size_t)(f * 4 + lg) * 16);
        }
        dst[0] = make_float4(__int_as_float(offA[0]), __int_as_float(offA[1]),
                             __int_as_float(offA[2]), __int_as_float(offA[3]));
        dst[1] = make_float4(__int_as_float(offB[0]), __int_as_float(offB[1]),
                             __int_as_float(offB[2]), __int_as_float(offB[3]));
        dst[6] = softcoef(args.cw1[layer] + (size_t)(f * 2 + a2) * 16);
        dst[7] = softcoef(args.cw1[layer] + (size_t)(f * 2 + b2) * 16);
        dst[8] = softcoef(args.cw2[layer] + (size_t)f * 16);
    }
    // transpose + binarize: x[b][784] -> xT[p][BPAD]
    if (tid < 784 * BPAD) {
        int b = tid & (BPAD - 1);
        int p = tid >> 7;
        float v = 0.f;
        if (b < BATCH) v = (args.x[b * 784 + p] > 0.5f) ? 1.f : 0.f;
        g_xT[p * BPAD + b] = v;
    }
}

// ============================================================================
// Conv(logic-tree) + 2x2 max-pool, feature-major, rewired tree.
// Block = one gate (8 warps). Warp = (batch-half, pool-position dd).
// Each warp: 8 coalesced float2 gathers + 7 gates; smem exchange; warps 0/1
// do the 4-way pool max and the coalesced store. 4x TLP vs one-item-per-warp.
// ============================================================================
template <int F, int POH, int POW, int WPAD, int OFSTR, int OW, int OHALO, int DOFF>
__global__ __launch_bounds__(256)
void conv_kernel(const float* __restrict__ in, float* __restrict__ out) {
    constexpr int NP = POH * POW;
    int gidx = blockIdx.x;                     // gate = (f, pi, pj)
    int w    = threadIdx.x >> 5;               // 0..7
    int lane = threadIdx.x & 31;
    int bh   = w >> 2;                         // batch half
    int dd   = w & 3;                          // pool position
    int b0   = bh * 64 + 2 * lane;

    int f = gidx / NP, r = gidx - f * NP;
    int pi = r / POW, pj = r - pi * POW;

    const float4* D = g_desc + DOFF + f * 9;
    float4 s0 = __ldg(D + 0), s1 = __ldg(D + 1);
    int oa[4] = {__float_as_int(s0.x), __float_as_int(s0.y),
                 __float_as_int(s0.z), __float_as_int(s0.w)};
    int ob[4] = {__float_as_int(s1.x), __float_as_int(s1.y),
                 __float_as_int(s1.z), __float_as_int(s1.w)};
    float4 kL[4] = {__ldg(D + 2), __ldg(D + 3), __ldg(D + 4), __ldg(D + 5)};
    float4 kMA = __ldg(D + 6), kMB = __ldg(D + 7), kT = __ldg(D + 8);

    int di = dd >> 1, dj = dd & 1;
    const float* src = in + ((2 * pi + di) * WPAD + 2 * pj + dj) * BPAD + b0;
    float2 A[4], Bv[4];
    #pragma unroll
    for (int g = 0; g < 4; g++) {
        A[g]  = __ldg((const float2*)(src + oa[g]));
        Bv[g] = __ldg((const float2*)(src + ob[g]));
    }
    float2 l0 = gate2(A[0], Bv[0], kL[0]);
    float2 l1 = gate2(A[1], Bv[1], kL[1]);
    float2 l2 = gate2(A[2], Bv[2], kL[2]);
    float2 l3 = gate2(A[3], Bv[3], kL[3]);
    float2 mA = gate2(l0, l1, kMA);
    float2 mB = gate2(l2, l3, kMB);
    float2 v  = gate2(mA, mB, kT);

    __shared__ float2 s_v[2][4][32];
    s_v[bh][dd][lane] = v;
    __syncthreads();

    if (w < 2) {
        float2 v0 = s_v[w][0][lane], v1 = s_v[w][1][lane];
        float2 v2 = s_v[w][2][lane], v3 = s_v[w][3][lane];
        float2 m;
        m.x = fmaxf(fmaxf(v0.x, v1.x), fmaxf(v2.x, v3.x));
        m.y = fmaxf(fmaxf(v0.y, v1.y), fmaxf(v2.y, v3.y));
        *(float2*)(out + (f * OFSTR + (pi + OHALO) * OW + (pj + OHALO)) * BPAD
                   + w * 64 + 2 * lane) = m;
    }
}

// ============================================================================
// FC layers: warp = output gate; lane = 4 batches (float4).
// ============================================================================
template <int DOUT, int COFF>
__global__ __launch_bounds__(256)
void fc_kernel(const float* __restrict__ inT, const int* __restrict__ idx,
               float* __restrict__ outT) {
    int o = blockIdx.x * 8 + (threadIdx.x >> 5);
    int b = (threadIdx.x & 31) * 4;
    int ia = __ldg(idx + o);
    int ib = __ldg(idx + DOUT + o);
    float4 k = g_coef[COFF + o];
    float4 a  = __ldg((const float4*)(inT + ia * BPAD + b));
    float4 bb = __ldg((const float4*)(inT + ib * BPAD + b));
    *(float4*)(outT + o * BPAD + b) = gate4(a, bb, k);
}

// fc3 + GroupSum(k=10, tau=30). grid = 10 groups, block 512 (16 warps).
__global__ __launch_bounds__(512)
void fc3_sum_kernel(const int* __restrict__ idx, float* __restrict__ out) {
    int grp = blockIdx.x;
    int tid = threadIdx.x;
    int lane = tid & 31;
    int w = tid >> 5;                      // 0..15
    int b = lane * 4;

    float4 acc = make_float4(0.f, 0.f, 0.f, 0.f);
    #pragma unroll 4
    for (int kk = 0; kk < 32; kk++) {
        int o = grp * 512 + w * 32 + kk;
        int ia = __ldg(idx + o);
        int ib = __ldg(idx + 5120 + o);
        float4 c = g_coef[OFF_FC3 + o];
        float4 a  = __ldg((const float4*)(g_f2T + ia * BPAD + b));
        float4 bb = __ldg((const float4*)(g_f2T + ib * BPAD + b));
        float4 v = gate4(a, bb, c);
        acc.x += v.x; acc.y += v.y; acc.z += v.z; acc.w += v.w;
    }
    __shared__ float4 sdata[16][32];
    sdata[w][lane] = acc;
    __syncthreads();
    if (w == 0) {
        float4 s = make_float4(0.f, 0.f, 0.f, 0.f);
        #pragma unroll
        for (int ww = 0; ww < 16; ww++) {
            float4 t = sdata[ww][lane];
            s.x += t.x; s.y += t.y; s.z += t.z; s.w += t.w;
        }
        const float inv = 1.0f / 30.0f;
        if (b     < BATCH) out[(b    ) * 10 + grp] = s.x * inv;
        if (b + 1 < BATCH) out[(b + 1) * 10 + grp] = s.y * inv;
        if (b + 2 < BATCH) out[(b + 2) * 10 + grp] = s.z * inv;
        if (b + 3 < BATCH) out[(b + 3) * 10 + grp] = s.w * inv;
    }
}

// ============================================================================
// Launch
// ============================================================================
extern "C" void kernel_launch(void* const* d_in, const int* in_sizes, int n_in,
                              void* d_out, int out_size) {
    PrepArgs pa;
    pa.x      = (const float*)d_in[0];
    pa.ci0[0] = (const int*)d_in[1];   pa.cw0[0] = (const float*)d_in[2];
    pa.ci1[0] = (const int*)d_in[3];   pa.cw1[0] = (const float*)d_in[4];
    pa.ci2[0] = (const int*)d_in[5];   pa.cw2[0] = (const float*)d_in[6];
    pa.ci0[1] = (const int*)d_in[7];   pa.cw0[1] = (const float*)d_in[8];
    pa.ci1[1] = (const int*)d_in[9];   pa.cw1[1] = (const float*)d_in[10];
    pa.ci2[1] = (const int*)d_in[11];  pa.cw2[1] = (const float*)d_in[12];
    pa.ci0[2] = (const int*)d_in[13];  pa.cw0[2] = (const float*)d_in[14];
    pa.ci1[2] = (const int*)d_in[15];  pa.cw1[2] = (const float*)d_in[16];
    pa.ci2[2] = (const int*)d_in[17];  pa.cw2[2] = (const float*)d_in[18];
    const int*   fc1i = (const int*)d_in[19];  pa.fc1w = (const float*)d_in[20];
    const int*   fc2i = (const int*)d_in[21];  pa.fc2w = (const float*)d_in[22];
    const int*   fc3i = (const int*)d_in[23];  pa.fc3w = (const float*)d_in[24];
    float* out = (float*)d_out;

    float *xT, *p1T, *p2T, *p3T, *f1T, *f2T;
    cudaGetSymbolAddress((void**)&xT,  g_xT);
    cudaGetSymbolAddress((void**)&p1T, g_p1T);
    cudaGetSymbolAddress((void**)&p2T, g_p2T);
    cudaGetSymbolAddress((void**)&p3T, g_p3T);
    cudaGetSymbolAddress((void**)&f1T, g_f1T);
    cudaGetSymbolAddress((void**)&f2T, g_f2T);

    // 1) prep (fc coefs + rewired conv descriptors) + transpose/binarize
    prep_kernel<<<(784 * BPAD + 255) / 256, 256>>>(pa);

    // 2) conv1 + pool: xT -> p1T.  Block per gate (8 warps).
    conv_kernel<16, 12, 12, 28, 196, 14, 1, DESC_C1>
        <<<16 * 144, 256>>>(xT, p1T);
    // 3) conv2 + pool
    conv_kernel<48, 6, 6, 14, 64, 8, 1, DESC_C2>
        <<<48 * 36, 256>>>(p1T, p2T);
    // 4) conv3 + pool
    conv_kernel<144, 3, 3, 8, 9, 3, 0, DESC_C3>
        <<<144 * 9, 256>>>(p2T, p3T);
    // 5) fc1: 1296 -> 20480 (warp per output, float4 lanes)
    fc_kernel<20480, OFF_FC1><<<20480 / 8, 256>>>(p3T, fc1i, f1T);
    // 6) fc2: 20480 -> 10240
    fc_kernel<10240, OFF_FC2><<<10240 / 8, 256>>>(f1T, fc2i, f2T);
    // 7) fc3 + group sum -> [100, 10]
    fc3_sum_kernel<<<10, 512>>>(fc3i, out);
    (void)in_sizes; (void)n_in; (void)out_size;
}

// round 15
// speedup vs baseline: 1.0617x; 1.0617x over previous
#include <cuda_runtime.h>

#define DEVINLINE __device__ __forceinline__

constexpr int BATCH = 100;
constexpr int BPAD  = 128;   // padded batch stride; lanes cover batches

// --- fc coefficient offsets (gates, float4 units) ---
constexpr int OFF_FC1 = 0;        // 20480
constexpr int OFF_FC2 = 20480;    // 10240
constexpr int OFF_FC3 = 30720;    // 5120
constexpr int N_FCC   = 35840;

// conv descriptor slots (float4 units): 9 slots per filter (rewired tree, no picks)
// [0]=offA0..3  [1]=offB0..3  [2..5]=leaf coefs  [6]=midA  [7]=midB  [8]=top
constexpr int DESC_C1 = 0;            // 16 filters
constexpr int DESC_C2 = 16 * 9;       // 48 filters
constexpr int DESC_C3 = 64 * 9;       // 144 filters

// --- scratch (device globals; zero-initialized; halo positions never written) ---
__device__ float4 g_coef[N_FCC];
__device__ float4 g_desc[208 * 9];
__device__ float  g_xT [784 * BPAD];            // binarized input, [pos][BPAD]
__device__ float  g_p1T[16 * 196 * BPAD];       // conv1 pooled, halo=1
__device__ float  g_p2T[48 * 64 * BPAD];        // conv2 pooled, halo=1
__device__ float  g_p3T[1296 * BPAD];           // conv3 pooled (ref flatten order)
__device__ float  g_f1T[20480 * BPAD];
__device__ float  g_f2T[10240 * BPAD];

// softmax(w[16]) -> fused gate coefficients (C, A, B, D):  op = C + A*a + B*b + D*ab
DEVINLINE float4 softcoef(const float* __restrict__ w) {
    const float4* w4 = (const float4*)w;
    float4 q0 = __ldg(w4 + 0), q1 = __ldg(w4 + 1), q2 = __ldg(w4 + 2), q3 = __ldg(w4 + 3);
    float v[16] = {q0.x, q0.y, q0.z, q0.w, q1.x, q1.y, q1.z, q1.w,
                   q2.x, q2.y, q2.z, q2.w, q3.x, q3.y, q3.z, q3.w};
    float mx = -1e30f;
    #pragma unroll
    for (int i = 0; i < 16; i++) mx = fmaxf(mx, v[i]);
    float sum = 0.f;
    #pragma unroll
    for (int i = 0; i < 16; i++) { v[i] = __expf(v[i] - mx); sum += v[i]; }
    float inv = 1.0f / sum;
    #pragma unroll
    for (int i = 0; i < 16; i++) v[i] *= inv;
    float C = v[8] + v[9] + v[10] + v[11] + v[12] + v[13] + v[14] + v[15];
    float A = v[2] + v[3] + v[6] + v[7] - v[8] - v[9] - v[12] - v[13];
    float B = v[4] + v[5] + v[6] + v[7] - v[8] - v[9] - v[10] - v[11];
    float D = v[1] - v[2] - v[4] - 2.f * v[6] - v[7]
            + v[8] + 2.f * v[9] + v[11] + v[13] - v[14];
    return make_float4(C, A, B, D);
}

DEVINLINE float2 gate2(float2 a, float2 b, float4 k) {
    float2 r;
    r.x = fmaf(a.x, fmaf(k.w, b.x, k.y), fmaf(k.z, b.x, k.x));
    r.y = fmaf(a.y, fmaf(k.w, b.y, k.y), fmaf(k.z, b.y, k.x));
    return r;
}
DEVINLINE float4 gate4(float4 a, float4 b, float4 k) {
    float4 r;
    r.x = fmaf(a.x, fmaf(k.w, b.x, k.y), fmaf(k.z, b.x, k.x));
    r.y = fmaf(a.y, fmaf(k.w, b.y, k.y), fmaf(k.z, b.y, k.x));
    r.z = fmaf(a.z, fmaf(k.w, b.z, k.y), fmaf(k.z, b.z, k.x));
    r.w = fmaf(a.w, fmaf(k.w, b.w, k.y), fmaf(k.z, b.w, k.x));
    return r;
}

// ============================================================================
// Prep kernel: fc coefficients + transpose/binarize + rewired conv descriptors.
// ============================================================================
struct PrepArgs {
    const float* x;
    const float* fc1w; const float* fc2w; const float* fc3w;
    const int*   ci0[3]; const int* ci1[3]; const int* ci2[3];
    const float* cw0[3]; const float* cw1[3]; const float* cw2[3];
};

__constant__ int c_F[3]    = {16, 48, 144};
__constant__ int c_KS[3]   = {5, 3, 3};
__constant__ int c_CSTR[3] = {784, 196, 64};
__constant__ int c_WPAD[3] = {28, 14, 8};
__constant__ int c_DOFF[3] = {DESC_C1, DESC_C2, DESC_C3};

__global__ void prep_kernel(PrepArgs args) {
    int tid = blockIdx.x * blockDim.x + threadIdx.x;
    if (tid < N_FCC) {
        const float* w;
        int g;
        if (tid < OFF_FC2)      { w = args.fc1w; g = tid; }
        else if (tid < OFF_FC3) { w = args.fc2w; g = tid - OFF_FC2; }
        else                    { w = args.fc3w; g = tid - OFF_FC3; }
        g_coef[tid] = softcoef(w + (size_t)g * 16);
    } else if (tid < N_FCC + 208) {
        int j = tid - N_FCC;
        int layer, f;
        if (j < 16)      { layer = 0; f = j; }
        else if (j < 64) { layer = 1; f = j - 16; }
        else             { layer = 2; f = j - 64; }

        int F = c_F[layer], KS = c_KS[layer], CSTR = c_CSTR[layer], WP = c_WPAD[layer];
        const int* i0 = args.ci0[layer];
        const int* i1 = args.ci1[layer];
        const int* i2 = args.ci2[layer];
        float4* dst = g_desc + c_DOFF[layer] + f * 9;

        int a2 = i2[f] & 1;                     // top-a mid index
        int b2 = i2[F + f] & 1;                 // top-b mid index

        // consumed mid-trees in order (duplicate if a2 == b2)
        int mids[2] = {a2, b2};
        int slots[4];   // leaf-gate index (0..3) per slot
        #pragma unroll
        for (int m = 0; m < 2; m++) {
            int mg = mids[m];
            slots[2 * m]     = i1[f * 2 + mg] & 3;          // mid's a-leaf
            slots[2 * m + 1] = i1[F * 2 + f * 2 + mg] & 3;  // mid's b-leaf
        }

        int offA[4], offB[4];
        #pragma unroll
        for (int s = 0; s < 4; s++) {
            int lg = slots[s];
            int ta = i0[f * 4 + lg], tb = i0[F * 4 + f * 4 + lg];
            int ca = ta / (KS * KS), ra = ta - ca * KS * KS;
            int cb = tb / (KS * KS), rb = tb - cb * KS * KS;
            offA[s] = (ca * CSTR + (ra / KS) * WP + (ra % KS)) * BPAD;
            offB[s] = (cb * CSTR + (rb / KS) * WP + (rb % KS)) * BPAD;
            dst[2 + s] = softcoef(args.cw0[layer] + (size_t)(f * 4 + lg) * 16);
        }
        dst[0] = make_float4(__int_as_float(offA[0]), __int_as_float(offA[1]),
                             __int_as_float(offA[2]), __int_as_float(offA[3]));
        dst[1] = make_float4(__int_as_float(offB[0]), __int_as_float(offB[1]),
                             __int_as_float(offB[2]), __int_as_float(offB[3]));
        dst[6] = softcoef(args.cw1[layer] + (size_t)(f * 2 + a2) * 16);
        dst[7] = softcoef(args.cw1[layer] + (size_t)(f * 2 + b2) * 16);
        dst[8] = softcoef(args.cw2[layer] + (size_t)f * 16);
    }
    // transpose + binarize: x[b][784] -> xT[p][BPAD]
    if (tid < 784 * BPAD) {
        int b = tid & (BPAD - 1);
        int p = tid >> 7;
        float v = 0.f;
        if (b < BATCH) v = (args.x[b * 784 + p] > 0.5f) ? 1.f : 0.f;
        g_xT[p * BPAD + b] = v;
    }
}

// ============================================================================
// Conv(logic-tree) + 2x2 max-pool, feature-major, rewired tree (no selects).
// warp = (gate, batch-half); lane = 2 batches (float2).
// ALL 32 gathers hoisted before any gate math (MLP = 32): one L2 round-trip
// instead of two serialized batches.
// ============================================================================
template <int F, int POH, int POW, int WPAD, int OFSTR, int OW, int OHALO, int DOFF>
__global__ __launch_bounds__(128)
void conv_kernel(const float* __restrict__ in, float* __restrict__ out) {
    int w = blockIdx.x * 4 + (threadIdx.x >> 5);   // global warp id
    int lane = threadIdx.x & 31;
    int gidx = w >> 1;                             // gate = (f, pi, pj)
    int b0 = (w & 1) * 64 + 2 * lane;

    constexpr int NP = POH * POW;
    int f = gidx / NP, r = gidx - f * NP;
    int pi = r / POW, pj = r - pi * POW;

    const float4* D = g_desc + DOFF + f * 9;
    float4 s0 = __ldg(D + 0), s1 = __ldg(D + 1);
    int oa[4] = {__float_as_int(s0.x), __float_as_int(s0.y),
                 __float_as_int(s0.z), __float_as_int(s0.w)};
    int ob[4] = {__float_as_int(s1.x), __float_as_int(s1.y),
                 __float_as_int(s1.z), __float_as_int(s1.w)};

    // hoist ALL 4 pool positions' gathers (32 loads in flight)
    float2 A[4][4], Bv[4][4];
    #pragma unroll
    for (int dd = 0; dd < 4; dd++) {
        const float* src = in + ((2 * pi + (dd >> 1)) * WPAD + 2 * pj + (dd & 1)) * BPAD + b0;
        #pragma unroll
        for (int g = 0; g < 4; g++) {
            A[dd][g]  = __ldg((const float2*)(src + oa[g]));
            Bv[dd][g] = __ldg((const float2*)(src + ob[g]));
        }
    }

    float4 kL0 = __ldg(D + 2), kL1 = __ldg(D + 3), kL2 = __ldg(D + 4), kL3 = __ldg(D + 5);
    float4 kMA = __ldg(D + 6), kMB = __ldg(D + 7), kT = __ldg(D + 8);

    float2 m;
    #pragma unroll
    for (int dd = 0; dd < 4; dd++) {
        float2 l0 = gate2(A[dd][0], Bv[dd][0], kL0);
        float2 l1 = gate2(A[dd][1], Bv[dd][1], kL1);
        float2 l2 = gate2(A[dd][2], Bv[dd][2], kL2);
        float2 l3 = gate2(A[dd][3], Bv[dd][3], kL3);
        float2 mA = gate2(l0, l1, kMA);
        float2 mB = gate2(l2, l3, kMB);
        float2 v  = gate2(mA, mB, kT);
        if (dd == 0) { m = v; }
        else { m.x = fmaxf(m.x, v.x); m.y = fmaxf(m.y, v.y); }
    }
    *(float2*)(out + (f * OFSTR + (pi + OHALO) * OW + (pj + OHALO)) * BPAD + b0) = m;
}

// ============================================================================
// FC layers: warp = output gate; lane = 4 batches (float4).
// ============================================================================
template <int DOUT, int COFF>
__global__ __launch_bounds__(256)
void fc_kernel(const float* __restrict__ inT, const int* __restrict__ idx,
               float* __restrict__ outT) {
    int o = blockIdx.x * 8 + (threadIdx.x >> 5);
    int b = (threadIdx.x & 31) * 4;
    int ia = __ldg(idx + o);
    int ib = __ldg(idx + DOUT + o);
    float4 k = g_coef[COFF + o];
    float4 a  = __ldg((const float4*)(inT + ia * BPAD + b));
    float4 bb = __ldg((const float4*)(inT + ib * BPAD + b));
    *(float4*)(outT + o * BPAD + b) = gate4(a, bb, k);
}

// fc3 + GroupSum(k=10, tau=30). grid = 10 groups, block 512 (16 warps).
__global__ __launch_bounds__(512)
void fc3_sum_kernel(const int* __restrict__ idx, float* __restrict__ out) {
    int grp = blockIdx.x;
    int tid = threadIdx.x;
    int lane = tid & 31;
    int w = tid >> 5;                      // 0..15
    int b = lane * 4;

    float4 acc = make_float4(0.f, 0.f, 0.f, 0.f);
    #pragma unroll 4
    for (int kk = 0; kk < 32; kk++) {
        int o = grp * 512 + w * 32 + kk;
        int ia = __ldg(idx + o);
        int ib = __ldg(idx + 5120 + o);
        float4 c = g_coef[OFF_FC3 + o];
        float4 a  = __ldg((const float4*)(g_f2T + ia * BPAD + b));
        float4 bb = __ldg((const float4*)(g_f2T + ib * BPAD + b));
        float4 v = gate4(a, bb, c);
        acc.x += v.x; acc.y += v.y; acc.z += v.z; acc.w += v.w;
    }
    __shared__ float4 sdata[16][32];
    sdata[w][lane] = acc;
    __syncthreads();
    if (w == 0) {
        float4 s = make_float4(0.f, 0.f, 0.f, 0.f);
        #pragma unroll
        for (int ww = 0; ww < 16; ww++) {
            float4 t = sdata[ww][lane];
            s.x += t.x; s.y += t.y; s.z += t.z; s.w += t.w;
        }
        const float inv = 1.0f / 30.0f;
        if (b     < BATCH) out[(b    ) * 10 + grp] = s.x * inv;
        if (b + 1 < BATCH) out[(b + 1) * 10 + grp] = s.y * inv;
        if (b + 2 < BATCH) out[(b + 2) * 10 + grp] = s.z * inv;
        if (b + 3 < BATCH) out[(b + 3) * 10 + grp] = s.w * inv;
    }
}

// ============================================================================
// Launch
// ============================================================================
extern "C" void kernel_launch(void* const* d_in, const int* in_sizes, int n_in,
                              void* d_out, int out_size) {
    PrepArgs pa;
    pa.x      = (const float*)d_in[0];
    pa.ci0[0] = (const int*)d_in[1];   pa.cw0[0] = (const float*)d_in[2];
    pa.ci1[0] = (const int*)d_in[3];   pa.cw1[0] = (const float*)d_in[4];
    pa.ci2[0] = (const int*)d_in[5];   pa.cw2[0] = (const float*)d_in[6];
    pa.ci0[1] = (const int*)d_in[7];   pa.cw0[1] = (const float*)d_in[8];
    pa.ci1[1] = (const int*)d_in[9];   pa.cw1[1] = (const float*)d_in[10];
    pa.ci2[1] = (const int*)d_in[11];  pa.cw2[1] = (const float*)d_in[12];
    pa.ci0[2] = (const int*)d_in[13];  pa.cw0[2] = (const float*)d_in[14];
    pa.ci1[2] = (const int*)d_in[15];  pa.cw1[2] = (const float*)d_in[16];
    pa.ci2[2] = (const int*)d_in[17];  pa.cw2[2] = (const float*)d_in[18];
    const int*   fc1i = (const int*)d_in[19];  pa.fc1w = (const float*)d_in[20];
    const int*   fc2i = (const int*)d_in[21];  pa.fc2w = (const float*)d_in[22];
    const int*   fc3i = (const int*)d_in[23];  pa.fc3w = (const float*)d_in[24];
    float* out = (float*)d_out;

    float *xT, *p1T, *p2T, *p3T, *f1T, *f2T;
    cudaGetSymbolAddress((void**)&xT,  g_xT);
    cudaGetSymbolAddress((void**)&p1T, g_p1T);
    cudaGetSymbolAddress((void**)&p2T, g_p2T);
    cudaGetSymbolAddress((void**)&p3T, g_p3T);
    cudaGetSymbolAddress((void**)&f1T, g_f1T);
    cudaGetSymbolAddress((void**)&f2T, g_f2T);

    // 1) prep (fc coefs + rewired conv descriptors) + transpose/binarize
    prep_kernel<<<(784 * BPAD + 255) / 256, 256>>>(pa);

    // 2) conv1 + pool: xT -> p1T (2304 gates x 2 batch-halves)
    conv_kernel<16, 12, 12, 28, 196, 14, 1, DESC_C1>
        <<<16 * 144 * 2 / 4, 128>>>(xT, p1T);
    // 3) conv2 + pool
    conv_kernel<48, 6, 6, 14, 64, 8, 1, DESC_C2>
        <<<48 * 36 * 2 / 4, 128>>>(p1T, p2T);
    // 4) conv3 + pool
    conv_kernel<144, 3, 3, 8, 9, 3, 0, DESC_C3>
        <<<144 * 9 * 2 / 4, 128>>>(p2T, p3T);
    // 5) fc1: 1296 -> 20480 (warp per output, float4 lanes)
    fc_kernel<20480, OFF_FC1><<<20480 / 8, 256>>>(p3T, fc1i, f1T);
    // 6) fc2: 20480 -> 10240
    fc_kernel<10240, OFF_FC2><<<10240 / 8, 256>>>(f1T, fc2i, f2T);
    // 7) fc3 + group sum -> [100, 10]
    fc3_sum_kernel<<<10, 512>>>(fc3i, out);
    (void)in_sizes; (void)n_in; (void)out_size;
}

// round 16
// speedup vs baseline: 1.4799x; 1.3939x over previous
#include <cuda_runtime.h>

#define DEVINLINE __device__ __forceinline__

constexpr int BATCH = 100;
constexpr int BPAD  = 128;   // padded batch stride; lanes cover batches

// conv descriptor slots (float4 units): 9 per filter
// [0]=offA0..3  [1]=offB0..3  [2..5]=leaf coefs  [6]=midA  [7]=midB  [8]=top
constexpr int DESC_C1 = 0;            // 16 filters
constexpr int DESC_C2 = 16 * 9;       // 48 filters
constexpr int DESC_C3 = 64 * 9;       // 144 filters

// --- scratch (device globals; zero-initialized; halo positions never written) ---
__device__ float4 g_desc [208 * 9];     // conv filter descriptors
__device__ float4 g_fdesc[5120 * 9];    // fused fc-tree descriptors (per fc3 gate)
__device__ float  g_xT [784 * BPAD];    // binarized input, [pos][BPAD]
__device__ float  g_p1T[16 * 196 * BPAD];   // conv1 pooled, halo=1
__device__ float  g_p2T[48 * 64 * BPAD];    // conv2 pooled, halo=1
__device__ float  g_p3T[1296 * BPAD];       // conv3 pooled (ref flatten order)
__device__ float  g_f3T[5120 * BPAD];       // fused fc output (pre group-sum)

// softmax(w[16]) -> fused gate coefficients (C, A, B, D):  op = C + A*a + B*b + D*ab
DEVINLINE float4 softcoef(const float* __restrict__ w) {
    const float4* w4 = (const float4*)w;
    float4 q0 = __ldg(w4 + 0), q1 = __ldg(w4 + 1), q2 = __ldg(w4 + 2), q3 = __ldg(w4 + 3);
    float v[16] = {q0.x, q0.y, q0.z, q0.w, q1.x, q1.y, q1.z, q1.w,
                   q2.x, q2.y, q2.z, q2.w, q3.x, q3.y, q3.z, q3.w};
    float mx = -1e30f;
    #pragma unroll
    for (int i = 0; i < 16; i++) mx = fmaxf(mx, v[i]);
    float sum = 0.f;
    #pragma unroll
    for (int i = 0; i < 16; i++) { v[i] = __expf(v[i] - mx); sum += v[i]; }
    float inv = 1.0f / sum;
    #pragma unroll
    for (int i = 0; i < 16; i++) v[i] *= inv;
    float C = v[8] + v[9] + v[10] + v[11] + v[12] + v[13] + v[14] + v[15];
    float A = v[2] + v[3] + v[6] + v[7] - v[8] - v[9] - v[12] - v[13];
    float B = v[4] + v[5] + v[6] + v[7] - v[8] - v[9] - v[10] - v[11];
    float D = v[1] - v[2] - v[4] - 2.f * v[6] - v[7]
            + v[8] + 2.f * v[9] + v[11] + v[13] - v[14];
    return make_float4(C, A, B, D);
}

DEVINLINE float2 gate2(float2 a, float2 b, float4 k) {
    float2 r;
    r.x = fmaf(a.x, fmaf(k.w, b.x, k.y), fmaf(k.z, b.x, k.x));
    r.y = fmaf(a.y, fmaf(k.w, b.y, k.y), fmaf(k.z, b.y, k.x));
    return r;
}
DEVINLINE float4 gate4(float4 a, float4 b, float4 k) {
    float4 r;
    r.x = fmaf(a.x, fmaf(k.w, b.x, k.y), fmaf(k.z, b.x, k.x));
    r.y = fmaf(a.y, fmaf(k.w, b.y, k.y), fmaf(k.z, b.y, k.x));
    r.z = fmaf(a.z, fmaf(k.w, b.z, k.y), fmaf(k.z, b.z, k.x));
    r.w = fmaf(a.w, fmaf(k.w, b.w, k.y), fmaf(k.z, b.w, k.x));
    return r;
}

// ============================================================================
// Prep: conv descriptors + fused fc-tree descriptors + transpose/binarize.
// ============================================================================
struct PrepArgs {
    const float* x;
    const float* fc1w; const float* fc2w; const float* fc3w;
    const int*   fc1i; const int*   fc2i; const int*   fc3i;
    const int*   ci0[3]; const int* ci1[3]; const int* ci2[3];
    const float* cw0[3]; const float* cw1[3]; const float* cw2[3];
};

__constant__ int c_F[3]    = {16, 48, 144};
__constant__ int c_KS[3]   = {5, 3, 3};
__constant__ int c_CSTR[3] = {784, 196, 64};
__constant__ int c_WPAD[3] = {28, 14, 8};
__constant__ int c_DOFF[3] = {DESC_C1, DESC_C2, DESC_C3};

__global__ void prep_kernel(PrepArgs args) {
    int tid = blockIdx.x * blockDim.x + threadIdx.x;
    if (tid < 208) {
        // ---- conv filter descriptor (rewired tree, straight-line eval) ----
        int layer, f;
        if (tid < 16)      { layer = 0; f = tid; }
        else if (tid < 64) { layer = 1; f = tid - 16; }
        else               { layer = 2; f = tid - 64; }

        int F = c_F[layer], KS = c_KS[layer], CSTR = c_CSTR[layer], WP = c_WPAD[layer];
        const int* i0 = args.ci0[layer];
        const int* i1 = args.ci1[layer];
        const int* i2 = args.ci2[layer];
        float4* dst = g_desc + c_DOFF[layer] + f * 9;

        int a2 = i2[f] & 1;
        int b2 = i2[F + f] & 1;
        int mids[2] = {a2, b2};
        int slots[4];
        #pragma unroll
        for (int m = 0; m < 2; m++) {
            int mg = mids[m];
            slots[2 * m]     = i1[f * 2 + mg] & 3;
            slots[2 * m + 1] = i1[F * 2 + f * 2 + mg] & 3;
        }
        int offA[4], offB[4];
        #pragma unroll
        for (int s = 0; s < 4; s++) {
            int lg = slots[s];
            int ta = i0[f * 4 + lg], tb = i0[F * 4 + f * 4 + lg];
            int ca = ta / (KS * KS), ra = ta - ca * KS * KS;
            int cb = tb / (KS * KS), rb = tb - cb * KS * KS;
            offA[s] = (ca * CSTR + (ra / KS) * WP + (ra % KS)) * BPAD;
            offB[s] = (cb * CSTR + (rb / KS) * WP + (rb % KS)) * BPAD;
            dst[2 + s] = softcoef(args.cw0[layer] + (size_t)(f * 4 + lg) * 16);
        }
        dst[0] = make_float4(__int_as_float(offA[0]), __int_as_float(offA[1]),
                             __int_as_float(offA[2]), __int_as_float(offA[3]));
        dst[1] = make_float4(__int_as_float(offB[0]), __int_as_float(offB[1]),
                             __int_as_float(offB[2]), __int_as_float(offB[3]));
        dst[6] = softcoef(args.cw1[layer] + (size_t)(f * 2 + a2) * 16);
        dst[7] = softcoef(args.cw1[layer] + (size_t)(f * 2 + b2) * 16);
        dst[8] = softcoef(args.cw2[layer] + (size_t)f * 16);
    } else if (tid < 208 + 5120) {
        // ---- fused fc-tree descriptor: fc3 gate o -> depth-3 tree over p3T ----
        int o = tid - 208;
        float4* dst = g_fdesc + o * 9;

        int m0 = args.fc3i[o];              // fc2 gate feeding top-a
        int m1 = args.fc3i[5120 + o];       // fc2 gate feeding top-b
        int l0 = args.fc2i[m0];             // fc1 gates (leaves)
        int l1 = args.fc2i[10240 + m0];
        int l2 = args.fc2i[m1];
        int l3 = args.fc2i[10240 + m1];
        int lv[4] = {l0, l1, l2, l3};

        int rA[4], rB[4];
        #pragma unroll
        for (int s = 0; s < 4; s++) {
            rA[s] = args.fc1i[lv[s]] * BPAD;            // p3T row offsets, prescaled
            rB[s] = args.fc1i[20480 + lv[s]] * BPAD;
            dst[2 + s] = softcoef(args.fc1w + (size_t)lv[s] * 16);
        }
        dst[0] = make_float4(__int_as_float(rA[0]), __int_as_float(rA[1]),
                             __int_as_float(rA[2]), __int_as_float(rA[3]));
        dst[1] = make_float4(__int_as_float(rB[0]), __int_as_float(rB[1]),
                             __int_as_float(rB[2]), __int_as_float(rB[3]));
        dst[6] = softcoef(args.fc2w + (size_t)m0 * 16);
        dst[7] = softcoef(args.fc2w + (size_t)m1 * 16);
        dst[8] = softcoef(args.fc3w + (size_t)o * 16);
    }
    // transpose + binarize: x[b][784] -> xT[p][BPAD]
    if (tid < 784 * BPAD) {
        int b = tid & (BPAD - 1);
        int p = tid >> 7;
        float v = 0.f;
        if (b < BATCH) v = (args.x[b * 784 + p] > 0.5f) ? 1.f : 0.f;
        g_xT[p * BPAD + b] = v;
    }
}

// ============================================================================
// Conv(logic-tree) + 2x2 max-pool, feature-major (R12 proven body).
// warp = (gate, batch-half); lane = 2 batches (float2). Loads hoisted per di.
// ============================================================================
template <int F, int POH, int POW, int WPAD, int OFSTR, int OW, int OHALO, int DOFF>
__global__ __launch_bounds__(128)
void conv_kernel(const float* __restrict__ in, float* __restrict__ out) {
    int w = blockIdx.x * 4 + (threadIdx.x >> 5);
    int lane = threadIdx.x & 31;
    int gidx = w >> 1;
    int b0 = (w & 1) * 64 + 2 * lane;

    constexpr int NP = POH * POW;
    int f = gidx / NP, r = gidx - f * NP;
    int pi = r / POW, pj = r - pi * POW;

    const float4* D = g_desc + DOFF + f * 9;
    float4 s0 = __ldg(D + 0), s1 = __ldg(D + 1);
    int oa[4] = {__float_as_int(s0.x), __float_as_int(s0.y),
                 __float_as_int(s0.z), __float_as_int(s0.w)};
    int ob[4] = {__float_as_int(s1.x), __float_as_int(s1.y),
                 __float_as_int(s1.z), __float_as_int(s1.w)};
    float4 kL[4] = {__ldg(D + 2), __ldg(D + 3), __ldg(D + 4), __ldg(D + 5)};
    float4 kMA = __ldg(D + 6), kMB = __ldg(D + 7), kT = __ldg(D + 8);

    float2 m = make_float2(-1e30f, -1e30f);
    #pragma unroll
    for (int di = 0; di < 2; di++) {
        float2 A[2][4], Bv[2][4];
        #pragma unroll
        for (int dj = 0; dj < 2; dj++) {
            const float* src = in + ((2 * pi + di) * WPAD + 2 * pj + dj) * BPAD + b0;
            #pragma unroll
            for (int g = 0; g < 4; g++) {
                A[dj][g]  = __ldg((const float2*)(src + oa[g]));
                Bv[dj][g] = __ldg((const float2*)(src + ob[g]));
            }
        }
        #pragma unroll
        for (int dj = 0; dj < 2; dj++) {
            float2 l0 = gate2(A[dj][0], Bv[dj][0], kL[0]);
            float2 l1 = gate2(A[dj][1], Bv[dj][1], kL[1]);
            float2 l2 = gate2(A[dj][2], Bv[dj][2], kL[2]);
            float2 l3 = gate2(A[dj][3], Bv[dj][3], kL[3]);
            float2 mA = gate2(l0, l1, kMA);
            float2 mB = gate2(l2, l3, kMB);
            float2 v  = gate2(mA, mB, kT);
            m.x = fmaxf(m.x, v.x);
            m.y = fmaxf(m.y, v.y);
        }
    }
    *(float2*)(out + (f * OFSTR + (pi + OHALO) * OW + (pj + OHALO)) * BPAD + b0) = m;
}

// ============================================================================
// Fused FC stack: fc1+fc2+fc3 as one depth-3 tree per fc3 gate.
// warp = fc3 gate (5120 warps); lane = 4 batches (float4).
// 8 coalesced gathers from hot p3T + 7 gates. Writes g_f3T.
// ============================================================================
__global__ __launch_bounds__(256)
void fcfused_kernel(const float* __restrict__ p3T, float* __restrict__ f3T) {
    int o = blockIdx.x * 8 + (threadIdx.x >> 5);   // 0..5119
    int b = (threadIdx.x & 31) * 4;

    const float4* D = g_fdesc + o * 9;
    float4 s0 = __ldg(D + 0), s1 = __ldg(D + 1);
    int rA[4] = {__float_as_int(s0.x), __float_as_int(s0.y),
                 __float_as_int(s0.z), __float_as_int(s0.w)};
    int rB[4] = {__float_as_int(s1.x), __float_as_int(s1.y),
                 __float_as_int(s1.z), __float_as_int(s1.w)};

    float4 A[4], Bv[4];
    #pragma unroll
    for (int g = 0; g < 4; g++) {
        A[g]  = __ldg((const float4*)(p3T + rA[g] + b));
        Bv[g] = __ldg((const float4*)(p3T + rB[g] + b));
    }
    float4 kL0 = __ldg(D + 2), kL1 = __ldg(D + 3), kL2 = __ldg(D + 4), kL3 = __ldg(D + 5);
    float4 kMA = __ldg(D + 6), kMB = __ldg(D + 7), kT = __ldg(D + 8);

    float4 l0 = gate4(A[0], Bv[0], kL0);
    float4 l1 = gate4(A[1], Bv[1], kL1);
    float4 l2 = gate4(A[2], Bv[2], kL2);
    float4 l3 = gate4(A[3], Bv[3], kL3);
    float4 mA = gate4(l0, l1, kMA);
    float4 mB = gate4(l2, l3, kMB);
    *(float4*)(f3T + o * BPAD + b) = gate4(mA, mB, kT);
}

// GroupSum(k=10, tau=30) over g_f3T. grid = 10 groups, block 512 (16 warps).
// Deterministic fixed-order reduction (same order as before).
__global__ __launch_bounds__(512)
void gsum_kernel(float* __restrict__ out) {
    int grp = blockIdx.x;
    int tid = threadIdx.x;
    int lane = tid & 31;
    int w = tid >> 5;                      // 0..15
    int b = lane * 4;

    float4 acc = make_float4(0.f, 0.f, 0.f, 0.f);
    #pragma unroll 8
    for (int kk = 0; kk < 32; kk++) {
        int o = grp * 512 + w * 32 + kk;
        float4 v = *(const float4*)(g_f3T + o * BPAD + b);
        acc.x += v.x; acc.y += v.y; acc.z += v.z; acc.w += v.w;
    }
    __shared__ float4 sdata[16][32];
    sdata[w][lane] = acc;
    __syncthreads();
    if (w == 0) {
        float4 s = make_float4(0.f, 0.f, 0.f, 0.f);
        #pragma unroll
        for (int ww = 0; ww < 16; ww++) {
            float4 t = sdata[ww][lane];
            s.x += t.x; s.y += t.y; s.z += t.z; s.w += t.w;
        }
        const float inv = 1.0f / 30.0f;
        if (b     < BATCH) out[(b    ) * 10 + grp] = s.x * inv;
        if (b + 1 < BATCH) out[(b + 1) * 10 + grp] = s.y * inv;
        if (b + 2 < BATCH) out[(b + 2) * 10 + grp] = s.z * inv;
        if (b + 3 < BATCH) out[(b + 3) * 10 + grp] = s.w * inv;
    }
}

// ============================================================================
// Launch
// ============================================================================
extern "C" void kernel_launch(void* const* d_in, const int* in_sizes, int n_in,
                              void* d_out, int out_size) {
    PrepArgs pa;
    pa.x      = (const float*)d_in[0];
    pa.ci0[0] = (const int*)d_in[1];   pa.cw0[0] = (const float*)d_in[2];
    pa.ci1[0] = (const int*)d_in[3];   pa.cw1[0] = (const float*)d_in[4];
    pa.ci2[0] = (const int*)d_in[5];   pa.cw2[0] = (const float*)d_in[6];
    pa.ci0[1] = (const int*)d_in[7];   pa.cw0[1] = (const float*)d_in[8];
    pa.ci1[1] = (const int*)d_in[9];   pa.cw1[1] = (const float*)d_in[10];
    pa.ci2[1] = (const int*)d_in[11];  pa.cw2[1] = (const float*)d_in[12];
    pa.ci0[2] = (const int*)d_in[13];  pa.cw0[2] = (const float*)d_in[14];
    pa.ci1[2] = (const int*)d_in[15];  pa.cw1[2] = (const float*)d_in[16];
    pa.ci2[2] = (const int*)d_in[17];  pa.cw2[2] = (const float*)d_in[18];
    pa.fc1i   = (const int*)d_in[19];  pa.fc1w   = (const float*)d_in[20];
    pa.fc2i   = (const int*)d_in[21];  pa.fc2w   = (const float*)d_in[22];
    pa.fc3i   = (const int*)d_in[23];  pa.fc3w   = (const float*)d_in[24];
    float* out = (float*)d_out;

    float *xT, *p1T, *p2T, *p3T, *f3T;
    cudaGetSymbolAddress((void**)&xT,  g_xT);
    cudaGetSymbolAddress((void**)&p1T, g_p1T);
    cudaGetSymbolAddress((void**)&p2T, g_p2T);
    cudaGetSymbolAddress((void**)&p3T, g_p3T);
    cudaGetSymbolAddress((void**)&f3T, g_f3T);

    // 1) prep: conv descs + fused fc-tree descs + transpose/binarize
    prep_kernel<<<(784 * BPAD + 255) / 256, 256>>>(pa);

    // 2) conv1 + pool: xT -> p1T (2304 gates x 2 batch-halves)
    conv_kernel<16, 12, 12, 28, 196, 14, 1, DESC_C1>
        <<<16 * 144 * 2 / 4, 128>>>(xT, p1T);
    // 3) conv2 + pool
    conv_kernel<48, 6, 6, 14, 64, 8, 1, DESC_C2>
        <<<48 * 36 * 2 / 4, 128>>>(p1T, p2T);
    // 4) conv3 + pool
    conv_kernel<144, 3, 3, 8, 9, 3, 0, DESC_C3>
        <<<144 * 9 * 2 / 4, 128>>>(p2T, p3T);
    // 5) fused fc1+fc2+fc3: p3T -> f3T (5120 warps)
    fcfused_kernel<<<5120 / 8, 256>>>(p3T, f3T);
    // 6) group sum -> [100, 10]
    gsum_kernel<<<10, 512>>>(out);
    (void)in_sizes; (void)n_in; (void)out_size;
}